// round 12
// baseline (speedup 1.0000x reference)
#include <cuda_runtime.h>
#include <cuda_bf16.h>
#include <cstdint>
#include <math.h>

#define SEQ 2048
#define BATCH 8
#define DIM 512
#define MTOT (BATCH*SEQ)      // 16384

// ---------------------------------------------------------------------------
// Scratch (allocation-free __device__ globals) — all splits stored [hi|lo]
// ---------------------------------------------------------------------------
__device__ __nv_bfloat16 g_Xs [(size_t)MTOT*2*DIM];     // X  [16384, 1024]
__device__ __nv_bfloat16 g_Wqs[(size_t)DIM*2*DIM];      // Wq^T [512, 1024]
__device__ __nv_bfloat16 g_Wks[(size_t)DIM*2*DIM];
__device__ __nv_bfloat16 g_Wvs[(size_t)DIM*2*DIM];
__device__ __nv_bfloat16 g_Qs [(size_t)MTOT*2*DIM];     // Q  [16384, 1024]
__device__ __nv_bfloat16 g_Ks [(size_t)MTOT*2*DIM];
__device__ __nv_bfloat16 g_Vts[(size_t)BATCH*DIM*2*SEQ];// V^T [8][512][4096]
__device__ float         g_S  [(size_t)BATCH*SEQ*SEQ];  // scores fp32
__device__ __nv_bfloat16 g_Ps [(size_t)MTOT*2*SEQ];     // probs [16384, 4096]

// ---------------------------------------------------------------------------
// Helpers
// ---------------------------------------------------------------------------
__device__ __forceinline__ uint32_t smem_u32(const void* p) {
    uint32_t a;
    asm("{ .reg .u64 t; cvta.to.shared.u64 t, %1; cvt.u32.u64 %0, t; }"
        : "=r"(a) : "l"(p));
    return a;
}
__device__ __forceinline__ void cp_async16(uint32_t saddr, const void* gaddr) {
    asm volatile("cp.async.cg.shared.global [%0], [%1], 16;"
                 :: "r"(saddr), "l"(gaddr) : "memory");
}
__device__ __forceinline__ void ldsm_x4(uint32_t& r0, uint32_t& r1,
                                        uint32_t& r2, uint32_t& r3, uint32_t a) {
    asm volatile("ldmatrix.sync.aligned.m8n8.x4.shared.b16 {%0,%1,%2,%3}, [%4];"
                 : "=r"(r0), "=r"(r1), "=r"(r2), "=r"(r3) : "r"(a));
}
__device__ __forceinline__ void mma_bf16(float* d, const uint32_t* a,
                                         const uint32_t* b) {
    asm volatile("mma.sync.aligned.m16n8k16.row.col.f32.bf16.bf16.f32 "
                 "{%0,%1,%2,%3}, {%4,%5,%6,%7}, {%8,%9}, {%0,%1,%2,%3};"
                 : "+f"(d[0]), "+f"(d[1]), "+f"(d[2]), "+f"(d[3])
                 : "r"(a[0]), "r"(a[1]), "r"(a[2]), "r"(a[3]),
                   "r"(b[0]), "r"(b[1]));
}
__device__ __forceinline__ void split2(float x, __nv_bfloat16& h, __nv_bfloat16& l) {
    h = __float2bfloat16(x);
    l = __float2bfloat16(x - __bfloat162float(h));
}
__device__ __forceinline__ uint2 pack4(__nv_bfloat16 a, __nv_bfloat16 b,
                                       __nv_bfloat16 c, __nv_bfloat16 d) {
    __nv_bfloat162 p0; p0.x = a; p0.y = b;
    __nv_bfloat162 p1; p1.x = c; p1.y = d;
    uint2 u; u.x = *(uint32_t*)&p0; u.y = *(uint32_t*)&p1;
    return u;
}
__device__ __forceinline__ uint32_t packbf2(__nv_bfloat16 a, __nv_bfloat16 b) {
    __nv_bfloat162 p; p.x = a; p.y = b;
    return *(uint32_t*)&p;
}

// ---------------------------------------------------------------------------
// bf16 mma.sync GEMM with logical->physical K-segment remap.
// Logical K' = 3*cps*64; physical storage = 2 segments [hi|lo].
// BM=128, BN=256, K-chunk=64 bf16. 256 thr / 8 warps, warp tile 64x64
// (2 m-warps x 4 n-warps). 3-stage cp.async pipeline (48KB/stage),
// ONE barrier per chunk. 1 CTA/SM (reg-heavy: 128 acc regs/thread).
// EPI: 0 = fp32 out, no bias
//      1 = split bf16 out [row*1024 + col | +512], column bias (z selects Q/K)
//      2 = split bf16 V^T out (batch-segmented cols), row bias
// ---------------------------------------------------------------------------
#define STAGE 49152          // 16KB A + 32KB B

__device__ __forceinline__ const char* chunk_ptr(
    const char* base, int c, int cps, int cps2,
    int m0_, int m1_, int m2_)
{
    int seg = (c >= cps) + (c >= cps2);
    int off = c - seg * cps;
    int m = (seg == 0) ? m0_ : ((seg == 1) ? m1_ : m2_);
    return base + (size_t)(m * cps + off) * 128;
}

__device__ __forceinline__ void load_chunk(
    uint32_t sdst, const char* Ac, const char* Bc,
    int ld_r, int ld_c, size_t ldab)
{
#pragma unroll
    for (int i = 0; i < 4; i++) {            // A: 128 rows x 128B
        int r = ld_r + i * 32;
        uint32_t so = r * 128 + ((ld_c ^ (r & 7)) * 16);
        cp_async16(sdst + so, Ac + (size_t)r * ldab + ld_c * 16);
    }
#pragma unroll
    for (int i = 0; i < 8; i++) {            // B: 256 rows x 128B
        int r = ld_r + i * 32;
        uint32_t so = r * 128 + ((ld_c ^ (r & 7)) * 16);
        cp_async16(sdst + 16384 + so, Bc + (size_t)r * ldab + ld_c * 16);
    }
}

template <int EPI>
__global__ void __launch_bounds__(256, 1) gemm_mma(
    const __nv_bfloat16* __restrict__ A, const __nv_bfloat16* __restrict__ B,
    const float* __restrict__ bias, void* __restrict__ Cv,
    const __nv_bfloat16* __restrict__ B2, const float* __restrict__ bias2,
    void* __restrict__ Cv2,
    int ldc, int NC, int cps,
    int mA0, int mA1, int mA2, int mB0, int mB1, int mB2,
    int ldabBytes, long sA, long sB, long sC)
{
    extern __shared__ __align__(16) char smem_raw[];
    uint32_t sraw = smem_u32(smem_raw);
    uint32_t sb = (sraw + 1023u) & ~1023u;   // 3 stages x 48KB

    const int tid = threadIdx.x;
    const int wid = tid >> 5, lid = tid & 31;
    const int wm = wid & 1;            // m-warp 0..1 (64 rows each)
    const int wn = wid >> 1;           // n-warp 0..3 (64 cols each)

    if (EPI == 1 && blockIdx.z == 1) { B = B2; bias = bias2; Cv = Cv2; }

    const int m0 = blockIdx.y * 128;
    const int n0 = blockIdx.x * 256;

    const char* Abase = (const char*)A + (size_t)blockIdx.z * sA * 2 +
                        (size_t)m0 * ldabBytes;
    const char* Bbase = (const char*)B + (size_t)blockIdx.z * sB * 2 +
                        (size_t)n0 * ldabBytes;
    const size_t ldab = (size_t)ldabBytes;
    const int cps2 = cps * 2;

    const int ld_r = tid >> 3;         // row 0..31, step 32
    const int ld_c = tid & 7;          // 16B chunk 0..7

    const int a_r = wm * 64 + ((lid >> 3) & 1) * 8 + (lid & 7);
    const int a_hi = lid >> 4;
    const int b_n = wn * 64 + ((lid >> 4) & 1) * 8 + (lid & 7);
    const int b_hi = (lid >> 3) & 1;

    float acc[4][8][4];
#pragma unroll
    for (int i = 0; i < 4; i++)
#pragma unroll
        for (int j = 0; j < 8; j++)
#pragma unroll
            for (int r = 0; r < 4; r++) acc[i][j][r] = 0.0f;

    // ---- prologue: stage chunks 0,1
#pragma unroll
    for (int p = 0; p < 2; p++) {
        if (p < NC)
            load_chunk(sb + p * STAGE,
                       chunk_ptr(Abase, p, cps, cps2, mA0, mA1, mA2),
                       chunk_ptr(Bbase, p, cps, cps2, mB0, mB1, mB2),
                       ld_r, ld_c, ldab);
        asm volatile("cp.async.commit_group;" ::: "memory");
    }

    int buf = 0;
    for (int c = 0; c < NC; c++) {
        asm volatile("cp.async.wait_group 1;" ::: "memory");
        __syncthreads();   // chunk c landed; all warps done reading buf (c-1)%3

        {
            int nb = buf + 2; if (nb >= 3) nb -= 3;
            if (c + 2 < NC)
                load_chunk(sb + nb * STAGE,
                           chunk_ptr(Abase, c + 2, cps, cps2, mA0, mA1, mA2),
                           chunk_ptr(Bbase, c + 2, cps, cps2, mB0, mB1, mB2),
                           ld_r, ld_c, ldab);
            asm volatile("cp.async.commit_group;" ::: "memory");
        }

        const uint32_t sa = sb + buf * STAGE;
        const uint32_t sbb = sa + 16384;

#pragma unroll
        for (int ks = 0; ks < 4; ks++) {
            uint32_t af[4][4], bfr[8][2];
#pragma unroll
            for (int mf = 0; mf < 4; mf++) {
                int r = a_r + mf * 16;
                uint32_t ad = sa + r * 128 + (((ks * 2 + a_hi) ^ (r & 7)) * 16);
                ldsm_x4(af[mf][0], af[mf][1], af[mf][2], af[mf][3], ad);
            }
#pragma unroll
            for (int p = 0; p < 4; p++) {
                int n = b_n + p * 16;
                uint32_t bd = sbb + n * 128 + (((ks * 2 + b_hi) ^ (n & 7)) * 16);
                ldsm_x4(bfr[2 * p][0], bfr[2 * p][1],
                        bfr[2 * p + 1][0], bfr[2 * p + 1][1], bd);
            }
#pragma unroll
            for (int mf = 0; mf < 4; mf++)
#pragma unroll
                for (int nf = 0; nf < 8; nf++)
                    mma_bf16(acc[mf][nf], af[mf], bfr[nf]);
        }
        buf = buf + 1; if (buf == 3) buf = 0;
    }

    // ---- epilogue (registers only; no smem)
    const int g = lid >> 2, t = lid & 3;
#pragma unroll
    for (int mf = 0; mf < 4; mf++) {
#pragma unroll
        for (int half = 0; half < 2; half++) {
            const int row = m0 + wm * 64 + mf * 16 + g + half * 8;
            float brow = (EPI == 2) ? bias[row] : 0.0f;
#pragma unroll
            for (int nf = 0; nf < 8; nf++) {
                const int col = n0 + wn * 64 + nf * 8 + t * 2;
                float vx = acc[mf][nf][half * 2 + 0];
                float vy = acc[mf][nf][half * 2 + 1];
                if (EPI == 0) {
                    float* C = (float*)Cv + (size_t)blockIdx.z * sC;
                    float2 v; v.x = vx; v.y = vy;
                    *(float2*)(C + (size_t)row * ldc + col) = v;
                } else if (EPI == 1) {
                    __nv_bfloat16* C = (__nv_bfloat16*)Cv;
                    vx += bias[col]; vy += bias[col + 1];
                    __nv_bfloat16 hx, lx, hy, ly;
                    split2(vx, hx, lx); split2(vy, hy, ly);
                    size_t base = (size_t)row * 1024 + col;
                    *(uint32_t*)(C + base)       = packbf2(hx, hy);
                    *(uint32_t*)(C + base + 512) = packbf2(lx, ly);
                } else {
                    // V^T split, batch-segmented columns
                    __nv_bfloat16* C = (__nv_bfloat16*)Cv;
                    vx += brow; vy += brow;
                    __nv_bfloat16 hx, lx, hy, ly;
                    split2(vx, hx, lx); split2(vy, hy, ly);
                    int b = col >> 11, ml = col & 2047;
                    size_t base = ((size_t)b * DIM + row) * 4096 + ml;
                    *(uint32_t*)(C + base)        = packbf2(hx, hy);
                    *(uint32_t*)(C + base + 2048) = packbf2(lx, ly);
                }
            }
        }
    }
}

// ---------------------------------------------------------------------------
// fp32 [R,512] -> bf16 [R, hi(512)|lo(512)]
// ---------------------------------------------------------------------------
__global__ void __launch_bounds__(256) conv_split(
    const float* __restrict__ in, __nv_bfloat16* __restrict__ out)
{
    int idx = blockIdx.x * 256 + threadIdx.x;         // float4 index
    int row = idx >> 7, c4 = idx & 127;
    float4 v = ((const float4*)in)[idx];
    __nv_bfloat16 h0, h1, h2, h3, l0, l1, l2, l3;
    split2(v.x, h0, l0); split2(v.y, h1, l1);
    split2(v.z, h2, l2); split2(v.w, h3, l3);
    size_t ob = (size_t)row * 1024 + c4 * 4;
    *(uint2*)(out + ob)       = pack4(h0, h1, h2, h3);
    *(uint2*)(out + ob + 512) = pack4(l0, l1, l2, l3);
}

// W [512,512] -> Ws [512 n-rows, hi(512)|lo(512)] transposed split.
__global__ void __launch_bounds__(256) conv_wt(
    const float* __restrict__ W, __nv_bfloat16* __restrict__ out)
{
    __shared__ float t[32][33];
    const int tx = threadIdx.x & 31, ty = threadIdx.x >> 5;   // 32 x 8
    const int k0 = (blockIdx.x & 15) * 32, n0 = (blockIdx.x >> 4) * 32;
#pragma unroll
    for (int i = 0; i < 32; i += 8)
        t[ty + i][tx] = W[(size_t)(k0 + ty + i) * 512 + (n0 + tx)];
    __syncthreads();
#pragma unroll
    for (int i = 0; i < 32; i += 8) {
        float v = t[tx][ty + i];   // = W[k0+tx][n0+ty+i]
        __nv_bfloat16 h, l;
        split2(v, h, l);
        size_t ob = (size_t)(n0 + ty + i) * 1024 + (k0 + tx);
        out[ob]       = h;
        out[ob + 512] = l;
    }
}

// ---------------------------------------------------------------------------
// Softmax over 2048-wide rows, fused split-bf16 [hi(2048)|lo(2048)] output
// ---------------------------------------------------------------------------
__global__ void __launch_bounds__(256) softmax_split(
    const float* __restrict__ S, __nv_bfloat16* __restrict__ Ps)
{
    const float* p = S + (size_t)blockIdx.x * SEQ;
    const int tid = threadIdx.x;
    const int wid = tid >> 5, lid = tid & 31;

    float4 v0 = ((const float4*)p)[tid];
    float4 v1 = ((const float4*)p)[tid + 256];

    __shared__ float red[8];

    float m = fmaxf(fmaxf(fmaxf(v0.x, v0.y), fmaxf(v0.z, v0.w)),
                    fmaxf(fmaxf(v1.x, v1.y), fmaxf(v1.z, v1.w)));
#pragma unroll
    for (int o = 16; o; o >>= 1) m = fmaxf(m, __shfl_xor_sync(~0u, m, o));
    if (lid == 0) red[wid] = m;
    __syncthreads();
    float rowmax = red[0];
#pragma unroll
    for (int i = 1; i < 8; i++) rowmax = fmaxf(rowmax, red[i]);
    __syncthreads();

    v0.x = __expf(v0.x - rowmax); v0.y = __expf(v0.y - rowmax);
    v0.z = __expf(v0.z - rowmax); v0.w = __expf(v0.w - rowmax);
    v1.x = __expf(v1.x - rowmax); v1.y = __expf(v1.y - rowmax);
    v1.z = __expf(v1.z - rowmax); v1.w = __expf(v1.w - rowmax);

    float sum = (v0.x + v0.y + v0.z + v0.w) + (v1.x + v1.y + v1.z + v1.w);
#pragma unroll
    for (int o = 16; o; o >>= 1) sum += __shfl_xor_sync(~0u, sum, o);
    if (lid == 0) red[wid] = sum;
    __syncthreads();
    float tot = 0.0f;
#pragma unroll
    for (int i = 0; i < 8; i++) tot += red[i];
    float inv = 1.0f / tot;

    size_t ob = (size_t)blockIdx.x * 4096;
    __nv_bfloat16 h0, h1, h2, h3, l0, l1, l2, l3;

    split2(v0.x * inv, h0, l0); split2(v0.y * inv, h1, l1);
    split2(v0.z * inv, h2, l2); split2(v0.w * inv, h3, l3);
    {
        size_t c = ob + tid * 4;
        *(uint2*)(Ps + c)        = pack4(h0, h1, h2, h3);
        *(uint2*)(Ps + c + 2048) = pack4(l0, l1, l2, l3);
    }
    split2(v1.x * inv, h0, l0); split2(v1.y * inv, h1, l1);
    split2(v1.z * inv, h2, l2); split2(v1.w * inv, h3, l3);
    {
        size_t c = ob + 1024 + tid * 4;
        *(uint2*)(Ps + c)        = pack4(h0, h1, h2, h3);
        *(uint2*)(Ps + c + 2048) = pack4(l0, l1, l2, l3);
    }
}

// ---------------------------------------------------------------------------
// kernel_launch: inputs = X, Wq, bq, Wk, bk, Wv, bv
// ---------------------------------------------------------------------------
extern "C" void kernel_launch(void* const* d_in, const int* in_sizes, int n_in,
                              void* d_out, int out_size)
{
    const float* X  = (const float*)d_in[0];
    const float* Wq = (const float*)d_in[1];
    const float* bq = (const float*)d_in[2];
    const float* Wk = (const float*)d_in[3];
    const float* bk = (const float*)d_in[4];
    const float* Wv = (const float*)d_in[5];
    const float* bv = (const float*)d_in[6];
    float* out = (float*)d_out;

    __nv_bfloat16 *Xs, *Wqs, *Wks, *Wvs, *Qs, *Ks, *Vts, *Ps;
    float *S;
    cudaGetSymbolAddress((void**)&Xs,  g_Xs);
    cudaGetSymbolAddress((void**)&Wqs, g_Wqs);
    cudaGetSymbolAddress((void**)&Wks, g_Wks);
    cudaGetSymbolAddress((void**)&Wvs, g_Wvs);
    cudaGetSymbolAddress((void**)&Qs,  g_Qs);
    cudaGetSymbolAddress((void**)&Ks,  g_Ks);
    cudaGetSymbolAddress((void**)&Vts, g_Vts);
    cudaGetSymbolAddress((void**)&S,   g_S);
    cudaGetSymbolAddress((void**)&Ps,  g_Ps);

    const int smemBytes = 1024 + 3 * STAGE;   // pad + 3 stages x (A16K+B32K)
    cudaFuncSetAttribute(gemm_mma<0>, cudaFuncAttributeMaxDynamicSharedMemorySize, smemBytes);
    cudaFuncSetAttribute(gemm_mma<1>, cudaFuncAttributeMaxDynamicSharedMemorySize, smemBytes);
    cudaFuncSetAttribute(gemm_mma<2>, cudaFuncAttributeMaxDynamicSharedMemorySize, smemBytes);

    // Launch 0-2: conversions needed by the merged QK projection
    conv_split<<<(MTOT * DIM / 4) / 256, 256>>>(X, Xs);
    conv_wt<<<256, 256>>>(Wq, Wqs);
    conv_wt<<<256, 256>>>(Wk, Wks);

    // Launch 3 (ncu capture slot): merged Q&K projections
    // (M=16384, N=512, K'=1536, cps=8; z=0 -> Q, z=1 -> K)
    gemm_mma<1><<<dim3(2, 128, 2), 256, smemBytes>>>(
        Xs, Wqs, bq, Qs, Wks, bk, Ks,
        0, 24, 8, 0, 1, 0, 0, 0, 1, 2048, 0, 0, 0);

    conv_wt<<<256, 256>>>(Wv, Wvs);

    // V^T = Wv^T @ X^T + bv(row)  (M=512, N=16384) -> batch-segmented split
    gemm_mma<2><<<dim3(64, 4, 1), 256, smemBytes>>>(
        Wvs, Xs, bv, Vts, nullptr, nullptr, nullptr,
        0, 24, 8, 0, 1, 0, 0, 0, 1, 2048, 0, 0, 0);

    // Scores: S[b] = Q[b] @ K[b]^T  (M=N=2048, K'=1536, cps=8, batched)
    gemm_mma<0><<<dim3(8, 16, 8), 256, smemBytes>>>(
        Qs, Ks, nullptr, S, nullptr, nullptr, nullptr,
        SEQ, 24, 8, 0, 1, 0, 0, 0, 1, 2048,
        (long)SEQ * 1024, (long)SEQ * 1024, (long)SEQ * SEQ);

    // Softmax + split P
    softmax_split<<<MTOT, 256>>>(S, Ps);

    // Out: O[b] = P[b] @ V[b]  (M=2048, N=512, K'=6144, cps=32, batched)
    gemm_mma<0><<<dim3(2, 16, 8), 256, smemBytes>>>(
        Ps, Vts, nullptr, out, nullptr, nullptr, nullptr,
        DIM, 96, 32, 0, 1, 0, 0, 0, 1, 8192,
        (long)SEQ * 4096, (long)DIM * 4096, (long)SEQ * DIM);
}

// round 16
// speedup vs baseline: 1.0613x; 1.0613x over previous
#include <cuda_runtime.h>
#include <cuda_bf16.h>
#include <cstdint>
#include <math.h>

#define SEQ 2048
#define BATCH 8
#define DIM 512
#define MTOT (BATCH*SEQ)      // 16384

// ---------------------------------------------------------------------------
// Scratch (allocation-free __device__ globals) — all splits stored [hi|lo]
// ---------------------------------------------------------------------------
__device__ __nv_bfloat16 g_Xs [(size_t)MTOT*2*DIM];     // X  [16384, 1024]
__device__ __nv_bfloat16 g_Wqs[(size_t)DIM*2*DIM];      // Wq^T [512, 1024]
__device__ __nv_bfloat16 g_Wks[(size_t)DIM*2*DIM];
__device__ __nv_bfloat16 g_Wvs[(size_t)DIM*2*DIM];
__device__ __nv_bfloat16 g_Qs [(size_t)MTOT*2*DIM];     // Q  [16384, 1024]
__device__ __nv_bfloat16 g_Ks [(size_t)MTOT*2*DIM];
__device__ __nv_bfloat16 g_Vts[(size_t)BATCH*DIM*2*SEQ];// V^T [8][512][4096]
__device__ float         g_S  [(size_t)BATCH*SEQ*SEQ];  // scores fp32
__device__ __nv_bfloat16 g_Ps [(size_t)MTOT*2*SEQ];     // probs [16384, 4096]

// ---------------------------------------------------------------------------
// Helpers
// ---------------------------------------------------------------------------
__device__ __forceinline__ uint32_t smem_u32(const void* p) {
    uint32_t a;
    asm("{ .reg .u64 t; cvta.to.shared.u64 t, %1; cvt.u32.u64 %0, t; }"
        : "=r"(a) : "l"(p));
    return a;
}
__device__ __forceinline__ void cp_async16(uint32_t saddr, const void* gaddr) {
    asm volatile("cp.async.cg.shared.global [%0], [%1], 16;"
                 :: "r"(saddr), "l"(gaddr) : "memory");
}
__device__ __forceinline__ void ldsm_x4(uint32_t& r0, uint32_t& r1,
                                        uint32_t& r2, uint32_t& r3, uint32_t a) {
    asm volatile("ldmatrix.sync.aligned.m8n8.x4.shared.b16 {%0,%1,%2,%3}, [%4];"
                 : "=r"(r0), "=r"(r1), "=r"(r2), "=r"(r3) : "r"(a));
}
__device__ __forceinline__ void mma_bf16(float* d, const uint32_t* a,
                                         const uint32_t* b) {
    asm volatile("mma.sync.aligned.m16n8k16.row.col.f32.bf16.bf16.f32 "
                 "{%0,%1,%2,%3}, {%4,%5,%6,%7}, {%8,%9}, {%0,%1,%2,%3};"
                 : "+f"(d[0]), "+f"(d[1]), "+f"(d[2]), "+f"(d[3])
                 : "r"(a[0]), "r"(a[1]), "r"(a[2]), "r"(a[3]),
                   "r"(b[0]), "r"(b[1]));
}
__device__ __forceinline__ void split2(float x, __nv_bfloat16& h, __nv_bfloat16& l) {
    h = __float2bfloat16(x);
    l = __float2bfloat16(x - __bfloat162float(h));
}
__device__ __forceinline__ uint2 pack4(__nv_bfloat16 a, __nv_bfloat16 b,
                                       __nv_bfloat16 c, __nv_bfloat16 d) {
    __nv_bfloat162 p0; p0.x = a; p0.y = b;
    __nv_bfloat162 p1; p1.x = c; p1.y = d;
    uint2 u; u.x = *(uint32_t*)&p0; u.y = *(uint32_t*)&p1;
    return u;
}
__device__ __forceinline__ uint32_t packbf2(__nv_bfloat16 a, __nv_bfloat16 b) {
    __nv_bfloat162 p; p.x = a; p.y = b;
    return *(uint32_t*)&p;
}

// Logical K chunk c -> physical segment pointer ([hi|lo] storage, 3-segment map)
__device__ __forceinline__ const char* chunk_ptr(
    const char* base, int c, int cps, int cps2,
    int m0_, int m1_, int m2_)
{
    int seg = (c >= cps) + (c >= cps2);
    int off = c - seg * cps;
    int m = (seg == 0) ? m0_ : ((seg == 1) ? m1_ : m2_);
    return base + (size_t)(m * cps + off) * 128;
}

// ===========================================================================
// Kernel A (R11-proven): 256 thr / 8 warps, warp tile 64x32, BM=BN=128,
// 3-stage cp.async pipeline, 2 CTAs/SM.  Used for PV and V^T GEMMs.
// EPI: 0 = fp32 out, no bias;  2 = split bf16 V^T out, row bias.
// ===========================================================================
__device__ __forceinline__ void load_chunk8(
    uint32_t sdst, const char* Ac, const char* Bc,
    int ld_r, int ld_c, size_t ldab)
{
#pragma unroll
    for (int i = 0; i < 4; i++) {
        int r = ld_r + i * 32;
        uint32_t so = r * 128 + ((ld_c ^ (r & 7)) * 16);
        cp_async16(sdst + so,         Ac + (size_t)r * ldab + ld_c * 16);
        cp_async16(sdst + 16384 + so, Bc + (size_t)r * ldab + ld_c * 16);
    }
}

template <int EPI>
__global__ void __launch_bounds__(256, 2) gemm_mma(
    const __nv_bfloat16* __restrict__ A, const __nv_bfloat16* __restrict__ B,
    const float* __restrict__ bias, void* __restrict__ Cv,
    int ldc, int NC, int cps,
    int ldabBytes, long sA, long sB, long sC)
{
    extern __shared__ __align__(16) char smem_raw[];
    uint32_t sraw = smem_u32(smem_raw);
    uint32_t sb = (sraw + 1023u) & ~1023u;   // 3 stages x 32KB

    const int tid = threadIdx.x;
    const int wid = tid >> 5, lid = tid & 31;
    const int wm = wid & 1;            // m-warp 0..1
    const int wn = wid >> 1;           // n-warp 0..3

    const int m0 = blockIdx.y * 128;
    const int n0 = blockIdx.x * 128;

    const char* Abase = (const char*)A + (size_t)blockIdx.z * sA * 2 +
                        (size_t)m0 * ldabBytes;
    const char* Bbase = (const char*)B + (size_t)blockIdx.z * sB * 2 +
                        (size_t)n0 * ldabBytes;
    const size_t ldab = (size_t)ldabBytes;
    const int cps2 = cps * 2;

    const int ld_r = tid >> 3;         // row 0..31, step 32
    const int ld_c = tid & 7;          // 16B chunk 0..7

    const int a_r = wm * 64 + ((lid >> 3) & 1) * 8 + (lid & 7);
    const int a_hi = lid >> 4;
    const int b_n = wn * 32 + ((lid >> 4) & 1) * 8 + (lid & 7);
    const int b_hi = (lid >> 3) & 1;

    float acc[4][4][4];
#pragma unroll
    for (int i = 0; i < 4; i++)
#pragma unroll
        for (int j = 0; j < 4; j++)
#pragma unroll
            for (int r = 0; r < 4; r++) acc[i][j][r] = 0.0f;

#pragma unroll
    for (int p = 0; p < 2; p++) {
        if (p < NC)
            load_chunk8(sb + p * 32768,
                        chunk_ptr(Abase, p, cps, cps2, 0, 1, 0),
                        chunk_ptr(Bbase, p, cps, cps2, 0, 0, 1),
                        ld_r, ld_c, ldab);
        asm volatile("cp.async.commit_group;" ::: "memory");
    }

    int buf = 0;
    for (int c = 0; c < NC; c++) {
        asm volatile("cp.async.wait_group 1;" ::: "memory");
        __syncthreads();

        {
            int nb = buf + 2; if (nb >= 3) nb -= 3;
            if (c + 2 < NC)
                load_chunk8(sb + nb * 32768,
                            chunk_ptr(Abase, c + 2, cps, cps2, 0, 1, 0),
                            chunk_ptr(Bbase, c + 2, cps, cps2, 0, 0, 1),
                            ld_r, ld_c, ldab);
            asm volatile("cp.async.commit_group;" ::: "memory");
        }

        const uint32_t sa = sb + buf * 32768;
        const uint32_t sbb = sa + 16384;

        uint32_t af[2][4][4], bfr[4][2];
#pragma unroll
        for (int mf = 0; mf < 4; mf++) {
            int r = a_r + mf * 16;
            uint32_t ad = sa + r * 128 + ((a_hi ^ (r & 7)) * 16);
            ldsm_x4(af[0][mf][0], af[0][mf][1], af[0][mf][2], af[0][mf][3], ad);
        }
#pragma unroll
        for (int ks = 0; ks < 4; ks++) {
            const int cur = ks & 1;
#pragma unroll
            for (int p = 0; p < 2; p++) {
                int n = b_n + p * 16;
                uint32_t bd = sbb + n * 128 + (((ks * 2 + b_hi) ^ (n & 7)) * 16);
                ldsm_x4(bfr[2 * p][0], bfr[2 * p][1],
                        bfr[2 * p + 1][0], bfr[2 * p + 1][1], bd);
            }
            if (ks < 3) {
#pragma unroll
                for (int mf = 0; mf < 4; mf++) {
                    int r = a_r + mf * 16;
                    uint32_t ad = sa + r * 128 +
                                  ((((ks + 1) * 2 + a_hi) ^ (r & 7)) * 16);
                    ldsm_x4(af[cur ^ 1][mf][0], af[cur ^ 1][mf][1],
                            af[cur ^ 1][mf][2], af[cur ^ 1][mf][3], ad);
                }
            }
#pragma unroll
            for (int mf = 0; mf < 4; mf++)
#pragma unroll
                for (int nf = 0; nf < 4; nf++)
                    mma_bf16(acc[mf][nf], af[cur][mf], bfr[nf]);
        }
        buf = buf + 1; if (buf == 3) buf = 0;
    }

    const int g = lid >> 2, t = lid & 3;
#pragma unroll
    for (int mf = 0; mf < 4; mf++) {
#pragma unroll
        for (int half = 0; half < 2; half++) {
            const int row = m0 + wm * 64 + mf * 16 + g + half * 8;
            float brow = (EPI == 2) ? bias[row] : 0.0f;
#pragma unroll
            for (int nf = 0; nf < 4; nf++) {
                const int col = n0 + wn * 32 + nf * 8 + t * 2;
                float vx = acc[mf][nf][half * 2 + 0];
                float vy = acc[mf][nf][half * 2 + 1];
                if (EPI == 0) {
                    float* C = (float*)Cv + (size_t)blockIdx.z * sC;
                    float2 v; v.x = vx; v.y = vy;
                    *(float2*)(C + (size_t)row * ldc + col) = v;
                } else {
                    __nv_bfloat16* C = (__nv_bfloat16*)Cv;
                    vx += brow; vy += brow;
                    __nv_bfloat16 hx, lx, hy, ly;
                    split2(vx, hx, lx); split2(vy, hy, ly);
                    int b = col >> 11, ml = col & 2047;
                    size_t base = ((size_t)b * DIM + row) * 4096 + ml;
                    *(uint32_t*)(C + base)        = packbf2(hx, hy);
                    *(uint32_t*)(C + base + 2048) = packbf2(lx, ly);
                }
            }
        }
    }
}

// ===========================================================================
// Kernel B: 128 thr / 4 warps (2x2), warp tile 64x64, BM=BN=128,
// 2-stage pipeline (65KB smem), 3 CTAs/SM.  Lower smem traffic per MMA.
// EPI: 0 = fp32 out, no bias;  1 = split bf16 [row*1024+col|+512], col bias
//      (blockIdx.z selects B/bias/C pair for merged Q&K).
// ===========================================================================
__device__ __forceinline__ void load_chunk4(
    uint32_t sdst, const char* Ac, const char* Bc,
    int ld_r, int ld_c, size_t ldab)
{
#pragma unroll
    for (int i = 0; i < 8; i++) {
        int r = ld_r + i * 16;
        uint32_t so = r * 128 + ((ld_c ^ (r & 7)) * 16);
        cp_async16(sdst + so,         Ac + (size_t)r * ldab + ld_c * 16);
        cp_async16(sdst + 16384 + so, Bc + (size_t)r * ldab + ld_c * 16);
    }
}

template <int EPI>
__global__ void __launch_bounds__(128, 3) gemm_mma4(
    const __nv_bfloat16* __restrict__ A, const __nv_bfloat16* __restrict__ B,
    const float* __restrict__ bias, void* __restrict__ Cv,
    const __nv_bfloat16* __restrict__ B2, const float* __restrict__ bias2,
    void* __restrict__ Cv2,
    int ldc, int NC, int cps,
    int ldabBytes, long sA, long sB, long sC)
{
    extern __shared__ __align__(16) char smem_raw[];
    uint32_t sraw = smem_u32(smem_raw);
    uint32_t sb = (sraw + 1023u) & ~1023u;   // 2 stages x 32KB

    const int tid = threadIdx.x;
    const int wid = tid >> 5, lid = tid & 31;
    const int wm = wid & 1;            // m-warp 0..1 (64 rows)
    const int wn = wid >> 1;           // n-warp 0..1 (64 cols)

    if (EPI == 1 && blockIdx.z == 1) { B = B2; bias = bias2; Cv = Cv2; }

    const int m0 = blockIdx.y * 128;
    const int n0 = blockIdx.x * 128;

    const char* Abase = (const char*)A + (size_t)blockIdx.z * sA * 2 +
                        (size_t)m0 * ldabBytes;
    const char* Bbase = (const char*)B + (size_t)blockIdx.z * sB * 2 +
                        (size_t)n0 * ldabBytes;
    const size_t ldab = (size_t)ldabBytes;
    const int cps2 = cps * 2;

    const int ld_r = tid >> 3;         // row 0..15, step 16
    const int ld_c = tid & 7;

    const int a_r = wm * 64 + ((lid >> 3) & 1) * 8 + (lid & 7);
    const int a_hi = lid >> 4;
    const int b_n = wn * 64 + ((lid >> 4) & 1) * 8 + (lid & 7);
    const int b_hi = (lid >> 3) & 1;

    float acc[4][8][4];
#pragma unroll
    for (int i = 0; i < 4; i++)
#pragma unroll
        for (int j = 0; j < 8; j++)
#pragma unroll
            for (int r = 0; r < 4; r++) acc[i][j][r] = 0.0f;

    // prologue: chunk 0 -> stage 0
    load_chunk4(sb,
                chunk_ptr(Abase, 0, cps, cps2, 0, 1, 0),
                chunk_ptr(Bbase, 0, cps, cps2, 0, 0, 1),
                ld_r, ld_c, ldab);
    asm volatile("cp.async.commit_group;" ::: "memory");

    for (int c = 0; c < NC; c++) {
        asm volatile("cp.async.wait_group 0;" ::: "memory");
        __syncthreads();   // chunk c landed; everyone done with other stage

        if (c + 1 < NC) {
            load_chunk4(sb + ((c + 1) & 1) * 32768,
                        chunk_ptr(Abase, c + 1, cps, cps2, 0, 1, 0),
                        chunk_ptr(Bbase, c + 1, cps, cps2, 0, 0, 1),
                        ld_r, ld_c, ldab);
        }
        asm volatile("cp.async.commit_group;" ::: "memory");

        const uint32_t sa = sb + (c & 1) * 32768;
        const uint32_t sbb = sa + 16384;

#pragma unroll
        for (int ks = 0; ks < 4; ks++) {
            uint32_t af[4][4];
#pragma unroll
            for (int mf = 0; mf < 4; mf++) {
                int r = a_r + mf * 16;
                uint32_t ad = sa + r * 128 + (((ks * 2 + a_hi) ^ (r & 7)) * 16);
                ldsm_x4(af[mf][0], af[mf][1], af[mf][2], af[mf][3], ad);
            }
#pragma unroll
            for (int p = 0; p < 4; p++) {
                uint32_t b0, b1, b2, b3;
                int n = b_n + p * 16;
                uint32_t bd = sbb + n * 128 + (((ks * 2 + b_hi) ^ (n & 7)) * 16);
                ldsm_x4(b0, b1, b2, b3, bd);
                uint32_t bl[2] = {b0, b1}, bh[2] = {b2, b3};
#pragma unroll
                for (int mf = 0; mf < 4; mf++) {
                    mma_bf16(acc[mf][2 * p],     af[mf], bl);
                    mma_bf16(acc[mf][2 * p + 1], af[mf], bh);
                }
            }
        }
    }

    const int g = lid >> 2, t = lid & 3;
#pragma unroll
    for (int mf = 0; mf < 4; mf++) {
#pragma unroll
        for (int half = 0; half < 2; half++) {
            const int row = m0 + wm * 64 + mf * 16 + g + half * 8;
#pragma unroll
            for (int nf = 0; nf < 8; nf++) {
                const int col = n0 + wn * 64 + nf * 8 + t * 2;
                float vx = acc[mf][nf][half * 2 + 0];
                float vy = acc[mf][nf][half * 2 + 1];
                if (EPI == 0) {
                    float* C = (float*)Cv + (size_t)blockIdx.z * sC;
                    float2 v; v.x = vx; v.y = vy;
                    *(float2*)(C + (size_t)row * ldc + col) = v;
                } else {
                    __nv_bfloat16* C = (__nv_bfloat16*)Cv;
                    vx += bias[col]; vy += bias[col + 1];
                    __nv_bfloat16 hx, lx, hy, ly;
                    split2(vx, hx, lx); split2(vy, hy, ly);
                    size_t base = (size_t)row * 1024 + col;
                    *(uint32_t*)(C + base)       = packbf2(hx, hy);
                    *(uint32_t*)(C + base + 512) = packbf2(lx, ly);
                }
            }
        }
    }
}

// ---------------------------------------------------------------------------
// fp32 [R,512] -> bf16 [R, hi(512)|lo(512)]
// ---------------------------------------------------------------------------
__global__ void __launch_bounds__(256) conv_split(
    const float* __restrict__ in, __nv_bfloat16* __restrict__ out)
{
    int idx = blockIdx.x * 256 + threadIdx.x;
    int row = idx >> 7, c4 = idx & 127;
    float4 v = ((const float4*)in)[idx];
    __nv_bfloat16 h0, h1, h2, h3, l0, l1, l2, l3;
    split2(v.x, h0, l0); split2(v.y, h1, l1);
    split2(v.z, h2, l2); split2(v.w, h3, l3);
    size_t ob = (size_t)row * 1024 + c4 * 4;
    *(uint2*)(out + ob)       = pack4(h0, h1, h2, h3);
    *(uint2*)(out + ob + 512) = pack4(l0, l1, l2, l3);
}

// Three W [512,512] -> Ws [512 n-rows, hi|lo] transposed splits in one launch.
__global__ void __launch_bounds__(256) conv_wt3(
    const float* __restrict__ W0, const float* __restrict__ W1,
    const float* __restrict__ W2,
    __nv_bfloat16* __restrict__ O0, __nv_bfloat16* __restrict__ O1,
    __nv_bfloat16* __restrict__ O2)
{
    const int which = blockIdx.x >> 8;
    const float* W = (which == 0) ? W0 : (which == 1) ? W1 : W2;
    __nv_bfloat16* out = (which == 0) ? O0 : (which == 1) ? O1 : O2;
    const int bid = blockIdx.x & 255;

    __shared__ float t[32][33];
    const int tx = threadIdx.x & 31, ty = threadIdx.x >> 5;
    const int k0 = (bid & 15) * 32, n0 = (bid >> 4) * 32;
#pragma unroll
    for (int i = 0; i < 32; i += 8)
        t[ty + i][tx] = W[(size_t)(k0 + ty + i) * 512 + (n0 + tx)];
    __syncthreads();
#pragma unroll
    for (int i = 0; i < 32; i += 8) {
        float v = t[tx][ty + i];
        __nv_bfloat16 h, l;
        split2(v, h, l);
        size_t ob = (size_t)(n0 + ty + i) * 1024 + (k0 + tx);
        out[ob]       = h;
        out[ob + 512] = l;
    }
}

// ---------------------------------------------------------------------------
// Softmax over 2048-wide rows, fused split-bf16 [hi(2048)|lo(2048)] output
// ---------------------------------------------------------------------------
__global__ void __launch_bounds__(256) softmax_split(
    const float* __restrict__ S, __nv_bfloat16* __restrict__ Ps)
{
    const float* p = S + (size_t)blockIdx.x * SEQ;
    const int tid = threadIdx.x;
    const int wid = tid >> 5, lid = tid & 31;

    float4 v0 = ((const float4*)p)[tid];
    float4 v1 = ((const float4*)p)[tid + 256];

    __shared__ float red[8];

    float m = fmaxf(fmaxf(fmaxf(v0.x, v0.y), fmaxf(v0.z, v0.w)),
                    fmaxf(fmaxf(v1.x, v1.y), fmaxf(v1.z, v1.w)));
#pragma unroll
    for (int o = 16; o; o >>= 1) m = fmaxf(m, __shfl_xor_sync(~0u, m, o));
    if (lid == 0) red[wid] = m;
    __syncthreads();
    float rowmax = red[0];
#pragma unroll
    for (int i = 1; i < 8; i++) rowmax = fmaxf(rowmax, red[i]);
    __syncthreads();

    v0.x = __expf(v0.x - rowmax); v0.y = __expf(v0.y - rowmax);
    v0.z = __expf(v0.z - rowmax); v0.w = __expf(v0.w - rowmax);
    v1.x = __expf(v1.x - rowmax); v1.y = __expf(v1.y - rowmax);
    v1.z = __expf(v1.z - rowmax); v1.w = __expf(v1.w - rowmax);

    float sum = (v0.x + v0.y + v0.z + v0.w) + (v1.x + v1.y + v1.z + v1.w);
#pragma unroll
    for (int o = 16; o; o >>= 1) sum += __shfl_xor_sync(~0u, sum, o);
    if (lid == 0) red[wid] = sum;
    __syncthreads();
    float tot = 0.0f;
#pragma unroll
    for (int i = 0; i < 8; i++) tot += red[i];
    float inv = 1.0f / tot;

    size_t ob = (size_t)blockIdx.x * 4096;
    __nv_bfloat16 h0, h1, h2, h3, l0, l1, l2, l3;

    split2(v0.x * inv, h0, l0); split2(v0.y * inv, h1, l1);
    split2(v0.z * inv, h2, l2); split2(v0.w * inv, h3, l3);
    {
        size_t c = ob + tid * 4;
        *(uint2*)(Ps + c)        = pack4(h0, h1, h2, h3);
        *(uint2*)(Ps + c + 2048) = pack4(l0, l1, l2, l3);
    }
    split2(v1.x * inv, h0, l0); split2(v1.y * inv, h1, l1);
    split2(v1.z * inv, h2, l2); split2(v1.w * inv, h3, l3);
    {
        size_t c = ob + 1024 + tid * 4;
        *(uint2*)(Ps + c)        = pack4(h0, h1, h2, h3);
        *(uint2*)(Ps + c + 2048) = pack4(l0, l1, l2, l3);
    }
}

// ---------------------------------------------------------------------------
// kernel_launch: inputs = X, Wq, bq, Wk, bk, Wv, bv
// ---------------------------------------------------------------------------
extern "C" void kernel_launch(void* const* d_in, const int* in_sizes, int n_in,
                              void* d_out, int out_size)
{
    const float* X  = (const float*)d_in[0];
    const float* Wq = (const float*)d_in[1];
    const float* bq = (const float*)d_in[2];
    const float* Wk = (const float*)d_in[3];
    const float* bk = (const float*)d_in[4];
    const float* Wv = (const float*)d_in[5];
    const float* bv = (const float*)d_in[6];
    float* out = (float*)d_out;

    __nv_bfloat16 *Xs, *Wqs, *Wks, *Wvs, *Qs, *Ks, *Vts, *Ps;
    float *S;
    cudaGetSymbolAddress((void**)&Xs,  g_Xs);
    cudaGetSymbolAddress((void**)&Wqs, g_Wqs);
    cudaGetSymbolAddress((void**)&Wks, g_Wks);
    cudaGetSymbolAddress((void**)&Wvs, g_Wvs);
    cudaGetSymbolAddress((void**)&Qs,  g_Qs);
    cudaGetSymbolAddress((void**)&Ks,  g_Ks);
    cudaGetSymbolAddress((void**)&Vts, g_Vts);
    cudaGetSymbolAddress((void**)&S,   g_S);
    cudaGetSymbolAddress((void**)&Ps,  g_Ps);

    const int smem8 = 1024 + 3 * 32768;   // kernel A: 3 stages
    const int smem4 = 1024 + 2 * 32768;   // kernel B: 2 stages
    cudaFuncSetAttribute(gemm_mma<0>,  cudaFuncAttributeMaxDynamicSharedMemorySize, smem8);
    cudaFuncSetAttribute(gemm_mma<2>,  cudaFuncAttributeMaxDynamicSharedMemorySize, smem8);
    cudaFuncSetAttribute(gemm_mma4<0>, cudaFuncAttributeMaxDynamicSharedMemorySize, smem4);
    cudaFuncSetAttribute(gemm_mma4<1>, cudaFuncAttributeMaxDynamicSharedMemorySize, smem4);

    // Conversions
    conv_split<<<(MTOT * DIM / 4) / 256, 256>>>(X, Xs);
    conv_wt3<<<768, 256>>>(Wq, Wk, Wv, Wqs, Wks, Wvs);

    // Merged Q&K projections (M=16384, N=512, K'=1536, cps=8; z selects Q/K)
    gemm_mma4<1><<<dim3(4, 128, 2), 128, smem4>>>(
        Xs, Wqs, bq, Qs, Wks, bk, Ks,
        0, 24, 8, 2048, 0, 0, 0);

    // V^T = Wv^T @ X^T + bv(row)  (M=512, N=16384) -> batch-segmented split
    gemm_mma<2><<<dim3(128, 4, 1), 256, smem8>>>(
        Wvs, Xs, bv, Vts, 0, 24, 8, 2048, 0, 0, 0);

    // Scores: S[b] = Q[b] @ K[b]^T  (M=N=2048, K'=1536, cps=8, batched)
    gemm_mma4<0><<<dim3(16, 16, 8), 128, smem4>>>(
        Qs, Ks, nullptr, S, nullptr, nullptr, nullptr,
        SEQ, 24, 8, 2048,
        (long)SEQ * 1024, (long)SEQ * 1024, (long)SEQ * SEQ);

    // Softmax + split P
    softmax_split<<<MTOT, 256>>>(S, Ps);

    // Out: O[b] = P[b] @ V[b]  (M=2048, N=512, K'=6144, cps=32, batched)
    gemm_mma<0><<<dim3(4, 16, 8), 256, smem8>>>(
        Ps, Vts, nullptr, out, DIM, 96, 32, 8192,
        (long)SEQ * 4096, (long)DIM * 4096, (long)SEQ * DIM);
}